// round 13
// baseline (speedup 1.0000x reference)
#include <cuda_runtime.h>
#include <cuda_fp16.h>
#include <cuda_bf16.h>
#include <cstdint>

// Problem constants (fixed by the dataset)
#define K_TOTAL   4096
#define N_TOTAL   11008
#define GROUP_SZ  128
#define M_TOTAL   8192          // 4*2048

// Element counts (dtype-invariant)
#define ELEMS_X      33554432   // 4*2048*4096
#define ELEMS_QW     45088768   // 11008*4096
#define ELEMS_SCALES 352256     // 11008*32
#define ELEMS_BIAS   11008

// Static device scratch
__device__ __half g_W[(size_t)N_TOTAL * K_TOTAL];   // dequantized weights, fp16
__device__ __half g_X[(size_t)ELEMS_X];             // x normalized to fp16
__device__ __half g_bias[ELEMS_BIAS];               // bias normalized to fp16

// ---------------------------------------------------------------------------
// dtype sniff: 0 = float32, 1 = float16, 2 = bfloat16
// ---------------------------------------------------------------------------
__device__ __forceinline__ int sniff_mode(const uint32_t* __restrict__ xr) {
    int half_votes = 0, small_votes = 0;
    #pragma unroll
    for (int i = 0; i < 64; i++) {
        uint32_t lo = xr[i] & 0xFFFFu;
        uint32_t e5 = (lo >> 10) & 31u;
        if (e5 >= 8u && e5 <= 20u) half_votes++;
        if (e5 <= 13u)             small_votes++;
    }
    if (half_votes < 52) return 0;
    return (small_votes >= 8) ? 1 : 2;
}

// ---------------------------------------------------------------------------
// Kernel 0a: normalize x -> g_X (fp16). Early-exit if x is already fp16.
// ---------------------------------------------------------------------------
__global__ __launch_bounds__(256) void conv_x_kernel(const void* __restrict__ xr)
{
    __shared__ int smode;
    if (threadIdx.x == 0) smode = sniff_mode((const uint32_t*)xr);
    __syncthreads();
    const int mode = smode;
    if (mode == 1) return;          // fp16 already: GEMM reads x directly

    size_t base = ((size_t)blockIdx.x * 256 + threadIdx.x) * 8;
    __half2 h[4];
    if (mode == 0) {
        float4 f0 = *((const float4*)((const float*)xr + base));
        float4 f1 = *((const float4*)((const float*)xr + base + 4));
        h[0] = __floats2half2_rn(f0.x, f0.y);
        h[1] = __floats2half2_rn(f0.z, f0.w);
        h[2] = __floats2half2_rn(f1.x, f1.y);
        h[3] = __floats2half2_rn(f1.z, f1.w);
    } else {
        const __nv_bfloat16* b = (const __nv_bfloat16*)xr + base;
        #pragma unroll
        for (int j = 0; j < 4; j++)
            h[j] = __floats2half2_rn(__bfloat162float(b[2*j]), __bfloat162float(b[2*j+1]));
    }
    *(uint4*)(g_X + base) = *(const uint4*)h;
}

// ---------------------------------------------------------------------------
// Kernel 0b: normalize bias -> g_bias (fp16)
// ---------------------------------------------------------------------------
__global__ __launch_bounds__(256) void conv_bias_kernel(const void* __restrict__ br,
                                                        const void* __restrict__ xr)
{
    __shared__ int smode;
    if (threadIdx.x == 0) smode = sniff_mode((const uint32_t*)xr);
    __syncthreads();
    const int mode = smode;

    int i = blockIdx.x * 256 + threadIdx.x;
    if (i >= ELEMS_BIAS) return;
    float v;
    if (mode == 0)      v = ((const float*)br)[i];
    else if (mode == 1) v = __half2float(((const __half*)br)[i]);
    else                v = __bfloat162float(((const __nv_bfloat16*)br)[i]);
    g_bias[i] = __float2half_rn(v);
}

// ---------------------------------------------------------------------------
// Kernel 1: dequantize  W = q * scale(group) + outlier  -> fp16
// ---------------------------------------------------------------------------
__global__ __launch_bounds__(256) void dequant_kernel(
    const void*  __restrict__ cand0,
    const void*  __restrict__ cand1,
    const float* __restrict__ scales)
{
    const uint32_t* u0 = (const uint32_t*)cand0;
    bool c0_is_q = (u0[0] < 16u) && (u0[1] < 16u) && (u0[2] < 16u) && (u0[3] < 16u);
    const int*   q       = c0_is_q ? (const int*)cand0   : (const int*)cand1;
    const float* outlier = c0_is_q ? (const float*)cand1 : (const float*)cand0;

    size_t idx = ((size_t)blockIdx.x * 256 + threadIdx.x) * 8;
    int o = (int)(idx / K_TOTAL);
    int i = (int)(idx % K_TOTAL);
    float s = scales[o * (K_TOTAL / GROUP_SZ) + (i / GROUP_SZ)];

    int4   q0 = *(const int4*)(q + idx);
    int4   q1 = *(const int4*)(q + idx + 4);
    float4 f0 = *(const float4*)(outlier + idx);
    float4 f1 = *(const float4*)(outlier + idx + 4);

    __half2 h[4];
    h[0] = __floats2half2_rn(fmaf((float)q0.x, s, f0.x), fmaf((float)q0.y, s, f0.y));
    h[1] = __floats2half2_rn(fmaf((float)q0.z, s, f0.z), fmaf((float)q0.w, s, f0.w));
    h[2] = __floats2half2_rn(fmaf((float)q1.x, s, f1.x), fmaf((float)q1.y, s, f1.y));
    h[3] = __floats2half2_rn(fmaf((float)q1.z, s, f1.z), fmaf((float)q1.w, s, f1.w));
    *(uint4*)(g_W + idx) = *(const uint4*)h;
}

// ===========================================================================
// Kernel 2: mma.sync GEMM. C[M,N] = X * W^T + bias
// CTA tile 128x256x64, 512 threads / 16 warps (warp tile 32x64, 4Mx4N),
// ldmatrix.x4 fragments, 4-stage cp.async pipeline (prefetch distance 3),
// padded smem stride (72 halfs), 1 CTA/SM (16 warps/SM).
// Grid: blockIdx.x walks M tiles (wavemates share the B tile in L2).
// ===========================================================================
#define BM 128
#define BN 256
#define BK 64
#define ASTR 72                                // 64 data + 8 pad halfs (144B)
#define STAGES 4
#define KITERS (K_TOTAL / BK)                  // 64
#define A_BYTES (BM * ASTR * 2)                // 18432
#define B_BYTES (BN * ASTR * 2)                // 36864
#define STAGE_BYTES (A_BYTES + B_BYTES)        // 55296
#define SMEM_GEMM (STAGES * STAGE_BYTES)       // 221184 (1 CTA/SM)

__device__ __forceinline__ uint32_t smem_u32(const void* p) {
    uint32_t a;
    asm("{ .reg .u64 t; cvta.to.shared.u64 t, %1; cvt.u32.u64 %0, t; }" : "=r"(a) : "l"(p));
    return a;
}
__device__ __forceinline__ void cp_async16(uint32_t sp, const void* gp) {
    asm volatile("cp.async.cg.shared.global [%0], [%1], 16;\n" :: "r"(sp), "l"(gp));
}
__device__ __forceinline__ void cp_commit() { asm volatile("cp.async.commit_group;\n"); }
__device__ __forceinline__ void cp_wait2()  { asm volatile("cp.async.wait_group 2;\n"); }
__device__ __forceinline__ void cp_wait0()  { asm volatile("cp.async.wait_group 0;\n"); }

__device__ __forceinline__ void ldsm_x4(uint32_t& r0, uint32_t& r1, uint32_t& r2,
                                        uint32_t& r3, uint32_t addr) {
    asm volatile("ldmatrix.sync.aligned.m8n8.x4.shared.b16 {%0,%1,%2,%3}, [%4];"
                 : "=r"(r0), "=r"(r1), "=r"(r2), "=r"(r3) : "r"(addr));
}
__device__ __forceinline__ void mma16816(float c[4], const uint32_t a[4],
                                         uint32_t b0, uint32_t b1) {
    asm volatile(
        "mma.sync.aligned.m16n8k16.row.col.f32.f16.f16.f32 "
        "{%0,%1,%2,%3}, {%4,%5,%6,%7}, {%8,%9}, {%0,%1,%2,%3};\n"
        : "+f"(c[0]), "+f"(c[1]), "+f"(c[2]), "+f"(c[3])
        : "r"(a[0]), "r"(a[1]), "r"(a[2]), "r"(a[3]), "r"(b0), "r"(b1));
}

__global__ __launch_bounds__(512, 1) void gemm_kernel(const void* __restrict__ xr,
                                                      void* __restrict__ outp)
{
    extern __shared__ __align__(1024) char smem[];
    __shared__ int smode;

    const int tid  = threadIdx.x;
    const int warp = tid >> 5;
    const int lane = tid & 31;
    const int wm   = warp & 3;           // 4 warp-rows (32 M-rows each)
    const int wn   = warp >> 2;          // 4 warp-cols (64 N-cols each)
    const int group = lane >> 2;
    const int tg    = lane & 3;

    if (tid == 0) smode = sniff_mode((const uint32_t*)xr);
    __syncthreads();                     // smode visible before A-pointer pick
    const int mode = smode;

    const uint32_t sbase = smem_u32(smem);
    const int bm0 = blockIdx.x * BM;     // x walks M: wavemates share B in L2
    const int bn0 = blockIdx.y * BN;
    const __half* Abase = (mode == 1) ? (const __half*)xr : g_X;
    const __half* gA = Abase + (size_t)bm0 * K_TOTAL;
    const __half* gB = g_W   + (size_t)bn0 * K_TOTAL;

    // ldmatrix.x4 lane mapping: lanes 0-15 rows 0-15 @k0, lanes 16-31 @k8
    const int lane_row  = ((lane >> 3) & 1) * 8 + (lane & 7);
    const int lane_kofs = (lane >> 4) * 8;

    uint32_t aoff[2], boff[4];
    #pragma unroll
    for (int mi = 0; mi < 2; mi++)
        aoff[mi] = ((wm * 32 + mi * 16 + lane_row) * ASTR + lane_kofs) * 2;
    #pragma unroll
    for (int j = 0; j < 4; j++)
        boff[j] = A_BYTES + ((wn * 64 + j * 16 + lane_row) * ASTR + lane_kofs) * 2;

    // cp.async per stage: A 1024 chunks (2/thread), B 2048 chunks (4/thread)
    auto load_stage = [&](int buf, int k0) {
        uint32_t sa = sbase + buf * STAGE_BYTES;
        uint32_t sb = sa + A_BYTES;
        #pragma unroll
        for (int t = 0; t < 2; t++) {
            int id = tid + t * 512;
            int row = id >> 3, c = id & 7;
            cp_async16(sa + row * (ASTR * 2) + c * 16,
                       gA + (size_t)row * K_TOTAL + k0 + c * 8);
        }
        #pragma unroll
        for (int t = 0; t < 4; t++) {
            int id = tid + t * 512;
            int row = id >> 3, c = id & 7;
            cp_async16(sb + row * (ASTR * 2) + c * 16,
                       gB + (size_t)row * K_TOTAL + k0 + c * 8);
        }
    };

    float acc[2][8][4];                  // 64 accumulator regs (warp 32x64)
    #pragma unroll
    for (int mi = 0; mi < 2; mi++)
        #pragma unroll
        for (int ni = 0; ni < 8; ni++)
            #pragma unroll
            for (int r = 0; r < 4; r++) acc[mi][ni][r] = 0.f;

    load_stage(0, 0);       cp_commit();
    load_stage(1, BK);      cp_commit();
    load_stage(2, 2 * BK);  cp_commit();

    for (int ks = 0; ks < KITERS; ks++) {
        const int s = ks & 3;
        cp_wait2();                 // stage ks resident (<=2 groups pending)
        __syncthreads();            // all warps finished stage (ks-1)

        const int ld = ks + 3;
        if (ld < KITERS) load_stage(ld & 3, ld * BK);
        cp_commit();                // empty group at tail keeps count aligned

        const uint32_t st = sbase + s * STAGE_BYTES;
        #pragma unroll
        for (int kk = 0; kk < 4; kk++) {     // BK=64 -> 4 k16 steps per barrier
            uint32_t a[2][4];
            #pragma unroll
            for (int mi = 0; mi < 2; mi++)
                ldsm_x4(a[mi][0], a[mi][1], a[mi][2], a[mi][3],
                        st + aoff[mi] + kk * 32);
            #pragma unroll
            for (int j = 0; j < 4; j++) {
                uint32_t r0, r1, r2, r3;
                ldsm_x4(r0, r1, r2, r3, st + boff[j] + kk * 32);
                #pragma unroll
                for (int mi = 0; mi < 2; mi++) {
                    mma16816(acc[mi][2*j],     a[mi], r0, r2);
                    mma16816(acc[mi][2*j + 1], a[mi], r1, r3);
                }
            }
        }
    }

    cp_wait0();

    // ---- Epilogue: bias add + dtype-dispatched direct writeout ----
    float2 bfb[8];
    #pragma unroll
    for (int ni = 0; ni < 8; ni++) {
        __half2 bh = *(const __half2*)(g_bias + bn0 + wn * 64 + ni * 8 + tg * 2);
        bfb[ni] = __half22float2(bh);
    }

    #pragma unroll
    for (int mi = 0; mi < 2; mi++) {
        int row0 = bm0 + wm * 32 + mi * 16 + group;
        #pragma unroll
        for (int ni = 0; ni < 8; ni++) {
            int col = bn0 + wn * 64 + ni * 8 + tg * 2;
            size_t o0 = (size_t)row0 * N_TOTAL + col;
            size_t o1 = (size_t)(row0 + 8) * N_TOTAL + col;
            float v00 = acc[mi][ni][0] + bfb[ni].x;
            float v01 = acc[mi][ni][1] + bfb[ni].y;
            float v10 = acc[mi][ni][2] + bfb[ni].x;
            float v11 = acc[mi][ni][3] + bfb[ni].y;
            if (mode == 1) {
                __half* O = (__half*)outp;
                *(__half2*)(O + o0) = __floats2half2_rn(v00, v01);
                *(__half2*)(O + o1) = __floats2half2_rn(v10, v11);
            } else if (mode == 0) {
                float* O = (float*)outp;
                *(float2*)(O + o0) = make_float2(v00, v01);
                *(float2*)(O + o1) = make_float2(v10, v11);
            } else {
                __nv_bfloat16* O = (__nv_bfloat16*)outp;
                *(__nv_bfloat162*)(O + o0) = __floats2bfloat162_rn(v00, v01);
                *(__nv_bfloat162*)(O + o1) = __floats2bfloat162_rn(v10, v11);
            }
        }
    }
}

// ---------------------------------------------------------------------------
// Launch
// ---------------------------------------------------------------------------
extern "C" void kernel_launch(void* const* d_in, const int* in_sizes, int n_in,
                              void* d_out, int out_size)
{
    const void* x      = nullptr;
    const void* bias   = nullptr;
    const float* scales = nullptr;
    const void* cand0  = nullptr;
    const void* cand1  = nullptr;

    for (int i = 0; i < n_in; i++) {
        long long s = in_sizes[i];
        if (s == ELEMS_X || s == 2LL*ELEMS_X || s == 4LL*ELEMS_X)               x = d_in[i];
        else if (s == ELEMS_BIAS || s == 2LL*ELEMS_BIAS || s == 4LL*ELEMS_BIAS) bias = d_in[i];
        else if (s == ELEMS_SCALES || s == 4LL*ELEMS_SCALES)                    scales = (const float*)d_in[i];
        else if (s == ELEMS_QW || s == 4LL*ELEMS_QW) {
            if (!cand0) cand0 = d_in[i]; else cand1 = d_in[i];
        }
    }
    if (!x || !bias || !scales || !cand0 || !cand1) {
        x      = d_in[0];
        cand0  = d_in[1];
        scales = (const float*)d_in[2];
        cand1  = d_in[3];
        bias   = d_in[4];
    }

    conv_x_kernel<<<ELEMS_X / (256 * 8), 256>>>(x);
    conv_bias_kernel<<<(ELEMS_BIAS + 255) / 256, 256>>>(bias, x);
    dequant_kernel<<<(int)((size_t)N_TOTAL * K_TOTAL / 8 / 256), 256>>>(cand0, cand1, scales);

    cudaFuncSetAttribute(gemm_kernel, cudaFuncAttributeMaxDynamicSharedMemorySize, SMEM_GEMM);
    dim3 grid(M_TOTAL / BM, N_TOTAL / BN);   // (64, 43): x walks M tiles
    gemm_kernel<<<grid, 512, SMEM_GEMM>>>(x, d_out);
}

// round 14
// speedup vs baseline: 1.0669x; 1.0669x over previous
#include <cuda_runtime.h>
#include <cuda_fp16.h>
#include <cuda_bf16.h>
#include <cstdint>

// Problem constants (fixed by the dataset)
#define K_TOTAL   4096
#define N_TOTAL   11008
#define GROUP_SZ  128
#define M_TOTAL   8192          // 4*2048

// Element counts (dtype-invariant)
#define ELEMS_X      33554432   // 4*2048*4096
#define ELEMS_QW     45088768   // 11008*4096
#define ELEMS_SCALES 352256     // 11008*32
#define ELEMS_BIAS   11008

// Static device scratch
__device__ __half g_W[(size_t)N_TOTAL * K_TOTAL];   // dequantized weights, fp16
__device__ __half g_X[(size_t)ELEMS_X];             // x normalized to fp16
__device__ __half g_bias[ELEMS_BIAS];               // bias normalized to fp16

// ---------------------------------------------------------------------------
// dtype sniff: 0 = float32, 1 = float16, 2 = bfloat16
// ---------------------------------------------------------------------------
__device__ __forceinline__ int sniff_mode(const uint32_t* __restrict__ xr) {
    int half_votes = 0, small_votes = 0;
    #pragma unroll
    for (int i = 0; i < 64; i++) {
        uint32_t lo = xr[i] & 0xFFFFu;
        uint32_t e5 = (lo >> 10) & 31u;
        if (e5 >= 8u && e5 <= 20u) half_votes++;
        if (e5 <= 13u)             small_votes++;
    }
    if (half_votes < 52) return 0;
    return (small_votes >= 8) ? 1 : 2;
}

// ---------------------------------------------------------------------------
// Kernel 0a: normalize x -> g_X (fp16). Early-exit if x is already fp16.
// ---------------------------------------------------------------------------
__global__ __launch_bounds__(256) void conv_x_kernel(const void* __restrict__ xr)
{
    __shared__ int smode;
    if (threadIdx.x == 0) smode = sniff_mode((const uint32_t*)xr);
    __syncthreads();
    const int mode = smode;
    if (mode == 1) return;          // fp16 already: GEMM reads x directly

    size_t base = ((size_t)blockIdx.x * 256 + threadIdx.x) * 8;
    __half2 h[4];
    if (mode == 0) {
        float4 f0 = *((const float4*)((const float*)xr + base));
        float4 f1 = *((const float4*)((const float*)xr + base + 4));
        h[0] = __floats2half2_rn(f0.x, f0.y);
        h[1] = __floats2half2_rn(f0.z, f0.w);
        h[2] = __floats2half2_rn(f1.x, f1.y);
        h[3] = __floats2half2_rn(f1.z, f1.w);
    } else {
        const __nv_bfloat16* b = (const __nv_bfloat16*)xr + base;
        #pragma unroll
        for (int j = 0; j < 4; j++)
            h[j] = __floats2half2_rn(__bfloat162float(b[2*j]), __bfloat162float(b[2*j+1]));
    }
    *(uint4*)(g_X + base) = *(const uint4*)h;
}

// ---------------------------------------------------------------------------
// Kernel 0b: normalize bias -> g_bias (fp16)
// ---------------------------------------------------------------------------
__global__ __launch_bounds__(256) void conv_bias_kernel(const void* __restrict__ br,
                                                        const void* __restrict__ xr)
{
    __shared__ int smode;
    if (threadIdx.x == 0) smode = sniff_mode((const uint32_t*)xr);
    __syncthreads();
    const int mode = smode;

    int i = blockIdx.x * 256 + threadIdx.x;
    if (i >= ELEMS_BIAS) return;
    float v;
    if (mode == 0)      v = ((const float*)br)[i];
    else if (mode == 1) v = __half2float(((const __half*)br)[i]);
    else                v = __bfloat162float(((const __nv_bfloat16*)br)[i]);
    g_bias[i] = __float2half_rn(v);
}

// ---------------------------------------------------------------------------
// Kernel 1: dequantize  W = q * scale(group) + outlier  -> fp16
// 16 elements/thread: 8 in-flight 16B loads per thread (MLP=8) to cover
// DRAM latency; 16 | 128 so one scale per thread.
// ---------------------------------------------------------------------------
__global__ __launch_bounds__(256) void dequant_kernel(
    const void*  __restrict__ cand0,
    const void*  __restrict__ cand1,
    const float* __restrict__ scales)
{
    const uint32_t* u0 = (const uint32_t*)cand0;
    bool c0_is_q = (u0[0] < 16u) && (u0[1] < 16u) && (u0[2] < 16u) && (u0[3] < 16u);
    const int*   q       = c0_is_q ? (const int*)cand0   : (const int*)cand1;
    const float* outlier = c0_is_q ? (const float*)cand1 : (const float*)cand0;

    size_t idx = ((size_t)blockIdx.x * 256 + threadIdx.x) * 16;
    int o = (int)(idx / K_TOTAL);
    int i = (int)(idx % K_TOTAL);
    float s = scales[o * (K_TOTAL / GROUP_SZ) + (i / GROUP_SZ)];

    int4   q0 = *(const int4*)(q + idx);
    int4   q1 = *(const int4*)(q + idx + 4);
    int4   q2 = *(const int4*)(q + idx + 8);
    int4   q3 = *(const int4*)(q + idx + 12);
    float4 f0 = *(const float4*)(outlier + idx);
    float4 f1 = *(const float4*)(outlier + idx + 4);
    float4 f2 = *(const float4*)(outlier + idx + 8);
    float4 f3 = *(const float4*)(outlier + idx + 12);

    __half2 h[8];
    h[0] = __floats2half2_rn(fmaf((float)q0.x, s, f0.x), fmaf((float)q0.y, s, f0.y));
    h[1] = __floats2half2_rn(fmaf((float)q0.z, s, f0.z), fmaf((float)q0.w, s, f0.w));
    h[2] = __floats2half2_rn(fmaf((float)q1.x, s, f1.x), fmaf((float)q1.y, s, f1.y));
    h[3] = __floats2half2_rn(fmaf((float)q1.z, s, f1.z), fmaf((float)q1.w, s, f1.w));
    h[4] = __floats2half2_rn(fmaf((float)q2.x, s, f2.x), fmaf((float)q2.y, s, f2.y));
    h[5] = __floats2half2_rn(fmaf((float)q2.z, s, f2.z), fmaf((float)q2.w, s, f2.w));
    h[6] = __floats2half2_rn(fmaf((float)q3.x, s, f3.x), fmaf((float)q3.y, s, f3.y));
    h[7] = __floats2half2_rn(fmaf((float)q3.z, s, f3.z), fmaf((float)q3.w, s, f3.w));
    *(uint4*)(g_W + idx)     = *(const uint4*)(h);
    *(uint4*)(g_W + idx + 8) = *(const uint4*)(h + 4);
}

// ===========================================================================
// Kernel 2: mma.sync GEMM (byte-exact R10 best: 2260.3 us).
// CTA tile 128x128x64, 8 warps (warp tile 32x64), ldmatrix.x4 fragments,
// 3-stage cp.async pipeline, padded smem stride (72 halfs), 2 CTAs/SM.
// Grid: blockIdx.x walks M tiles (wavemates share the B tile in L2).
// ===========================================================================
#define BM 128
#define BN 128
#define BK 64
#define ASTR 72                                // 64 data + 8 pad halfs (144B)
#define STAGES 3
#define KITERS (K_TOTAL / BK)                  // 64
#define A_BYTES (BM * ASTR * 2)                // 18432
#define B_BYTES (BN * ASTR * 2)                // 18432
#define STAGE_BYTES (A_BYTES + B_BYTES)        // 36864
#define SMEM_GEMM (STAGES * STAGE_BYTES)       // 110592 (2 CTAs: 216KB < 228KB)

__device__ __forceinline__ uint32_t smem_u32(const void* p) {
    uint32_t a;
    asm("{ .reg .u64 t; cvta.to.shared.u64 t, %1; cvt.u32.u64 %0, t; }" : "=r"(a) : "l"(p));
    return a;
}
__device__ __forceinline__ void cp_async16(uint32_t sp, const void* gp) {
    asm volatile("cp.async.cg.shared.global [%0], [%1], 16;\n" :: "r"(sp), "l"(gp));
}
__device__ __forceinline__ void cp_commit() { asm volatile("cp.async.commit_group;\n"); }
__device__ __forceinline__ void cp_wait1()  { asm volatile("cp.async.wait_group 1;\n"); }
__device__ __forceinline__ void cp_wait0()  { asm volatile("cp.async.wait_group 0;\n"); }

__device__ __forceinline__ void ldsm_x4(uint32_t& r0, uint32_t& r1, uint32_t& r2,
                                        uint32_t& r3, uint32_t addr) {
    asm volatile("ldmatrix.sync.aligned.m8n8.x4.shared.b16 {%0,%1,%2,%3}, [%4];"
                 : "=r"(r0), "=r"(r1), "=r"(r2), "=r"(r3) : "r"(addr));
}
__device__ __forceinline__ void mma16816(float c[4], const uint32_t a[4],
                                         uint32_t b0, uint32_t b1) {
    asm volatile(
        "mma.sync.aligned.m16n8k16.row.col.f32.f16.f16.f32 "
        "{%0,%1,%2,%3}, {%4,%5,%6,%7}, {%8,%9}, {%0,%1,%2,%3};\n"
        : "+f"(c[0]), "+f"(c[1]), "+f"(c[2]), "+f"(c[3])
        : "r"(a[0]), "r"(a[1]), "r"(a[2]), "r"(a[3]), "r"(b0), "r"(b1));
}

__global__ __launch_bounds__(256, 2) void gemm_kernel(const void* __restrict__ xr,
                                                      void* __restrict__ outp)
{
    extern __shared__ __align__(1024) char smem[];
    __shared__ int smode;

    const int tid  = threadIdx.x;
    const int warp = tid >> 5;
    const int lane = tid & 31;
    const int wm   = warp & 3;           // 4 warps along M (32 rows)
    const int wn   = warp >> 2;          // 2 warps along N (64 cols)
    const int group = lane >> 2;
    const int tg    = lane & 3;

    if (tid == 0) smode = sniff_mode((const uint32_t*)xr);
    __syncthreads();                     // smode visible before A-pointer pick
    const int mode = smode;

    const uint32_t sbase = smem_u32(smem);
    const int bm0 = blockIdx.x * BM;     // x walks M: wavemates share B in L2
    const int bn0 = blockIdx.y * BN;
    const __half* Abase = (mode == 1) ? (const __half*)xr : g_X;
    const __half* gA = Abase + (size_t)bm0 * K_TOTAL;
    const __half* gB = g_W   + (size_t)bn0 * K_TOTAL;

    // ldmatrix.x4 lane mapping: lanes 0-15 rows 0-15 @k0, lanes 16-31 @k8
    const int lane_row  = ((lane >> 3) & 1) * 8 + (lane & 7);
    const int lane_kofs = (lane >> 4) * 8;

    uint32_t aoff[2], boff[4];
    #pragma unroll
    for (int mi = 0; mi < 2; mi++)
        aoff[mi] = ((wm * 32 + mi * 16 + lane_row) * ASTR + lane_kofs) * 2;
    #pragma unroll
    for (int j = 0; j < 4; j++)
        boff[j] = A_BYTES + ((wn * 64 + j * 16 + lane_row) * ASTR + lane_kofs) * 2;

    // cp.async per stage: A 1024 chunks (4/thread), B 1024 chunks (4/thread)
    auto load_stage = [&](int buf, int k0) {
        uint32_t sa = sbase + buf * STAGE_BYTES;
        uint32_t sb = sa + A_BYTES;
        #pragma unroll
        for (int t = 0; t < 4; t++) {
            int id = tid + t * 256;
            int row = id >> 3, c = id & 7;
            cp_async16(sa + row * (ASTR * 2) + c * 16,
                       gA + (size_t)row * K_TOTAL + k0 + c * 8);
            cp_async16(sb + row * (ASTR * 2) + c * 16,
                       gB + (size_t)row * K_TOTAL + k0 + c * 8);
        }
    };

    float acc[2][8][4];
    #pragma unroll
    for (int mi = 0; mi < 2; mi++)
        #pragma unroll
        for (int ni = 0; ni < 8; ni++)
            #pragma unroll
            for (int r = 0; r < 4; r++) acc[mi][ni][r] = 0.f;

    load_stage(0, 0);       cp_commit();
    load_stage(1, BK);      cp_commit();

    for (int ks = 0; ks < KITERS; ks++) {
        const int s = ks % STAGES;
        cp_wait1();                 // stage ks resident (<=1 group pending)
        __syncthreads();            // all warps finished stage (ks-1)

        const int ld = ks + 2;
        if (ld < KITERS) load_stage(ld % STAGES, ld * BK);
        cp_commit();                // empty group at tail keeps count aligned

        const uint32_t st = sbase + s * STAGE_BYTES;
        #pragma unroll
        for (int kk = 0; kk < 4; kk++) {     // BK=64 -> 4 k16 steps per barrier
            uint32_t a[2][4];
            #pragma unroll
            for (int mi = 0; mi < 2; mi++)
                ldsm_x4(a[mi][0], a[mi][1], a[mi][2], a[mi][3],
                        st + aoff[mi] + kk * 32);
            #pragma unroll
            for (int j = 0; j < 4; j++) {
                uint32_t r0, r1, r2, r3;
                ldsm_x4(r0, r1, r2, r3, st + boff[j] + kk * 32);
                #pragma unroll
                for (int mi = 0; mi < 2; mi++) {
                    mma16816(acc[mi][2*j],     a[mi], r0, r2);
                    mma16816(acc[mi][2*j + 1], a[mi], r1, r3);
                }
            }
        }
    }

    cp_wait0();

    // ---- Epilogue: bias add + dtype-dispatched direct writeout ----
    float2 bfb[8];
    #pragma unroll
    for (int ni = 0; ni < 8; ni++) {
        __half2 bh = *(const __half2*)(g_bias + bn0 + wn * 64 + ni * 8 + tg * 2);
        bfb[ni] = __half22float2(bh);
    }

    #pragma unroll
    for (int mi = 0; mi < 2; mi++) {
        int row0 = bm0 + wm * 32 + mi * 16 + group;
        #pragma unroll
        for (int ni = 0; ni < 8; ni++) {
            int col = bn0 + wn * 64 + ni * 8 + tg * 2;
            size_t o0 = (size_t)row0 * N_TOTAL + col;
            size_t o1 = (size_t)(row0 + 8) * N_TOTAL + col;
            float v00 = acc[mi][ni][0] + bfb[ni].x;
            float v01 = acc[mi][ni][1] + bfb[ni].y;
            float v10 = acc[mi][ni][2] + bfb[ni].x;
            float v11 = acc[mi][ni][3] + bfb[ni].y;
            if (mode == 1) {
                __half* O = (__half*)outp;
                *(__half2*)(O + o0) = __floats2half2_rn(v00, v01);
                *(__half2*)(O + o1) = __floats2half2_rn(v10, v11);
            } else if (mode == 0) {
                float* O = (float*)outp;
                *(float2*)(O + o0) = make_float2(v00, v01);
                *(float2*)(O + o1) = make_float2(v10, v11);
            } else {
                __nv_bfloat16* O = (__nv_bfloat16*)outp;
                *(__nv_bfloat162*)(O + o0) = __floats2bfloat162_rn(v00, v01);
                *(__nv_bfloat162*)(O + o1) = __floats2bfloat162_rn(v10, v11);
            }
        }
    }
}

// ---------------------------------------------------------------------------
// Launch
// ---------------------------------------------------------------------------
extern "C" void kernel_launch(void* const* d_in, const int* in_sizes, int n_in,
                              void* d_out, int out_size)
{
    const void* x      = nullptr;
    const void* bias   = nullptr;
    const float* scales = nullptr;
    const void* cand0  = nullptr;
    const void* cand1  = nullptr;

    for (int i = 0; i < n_in; i++) {
        long long s = in_sizes[i];
        if (s == ELEMS_X || s == 2LL*ELEMS_X || s == 4LL*ELEMS_X)               x = d_in[i];
        else if (s == ELEMS_BIAS || s == 2LL*ELEMS_BIAS || s == 4LL*ELEMS_BIAS) bias = d_in[i];
        else if (s == ELEMS_SCALES || s == 4LL*ELEMS_SCALES)                    scales = (const float*)d_in[i];
        else if (s == ELEMS_QW || s == 4LL*ELEMS_QW) {
            if (!cand0) cand0 = d_in[i]; else cand1 = d_in[i];
        }
    }
    if (!x || !bias || !scales || !cand0 || !cand1) {
        x      = d_in[0];
        cand0  = d_in[1];
        scales = (const float*)d_in[2];
        cand1  = d_in[3];
        bias   = d_in[4];
    }

    conv_x_kernel<<<ELEMS_X / (256 * 8), 256>>>(x);
    conv_bias_kernel<<<(ELEMS_BIAS + 255) / 256, 256>>>(bias, x);
    dequant_kernel<<<(int)((size_t)N_TOTAL * K_TOTAL / 16 / 256), 256>>>(cand0, cand1, scales);

    cudaFuncSetAttribute(gemm_kernel, cudaFuncAttributeMaxDynamicSharedMemorySize, SMEM_GEMM);
    dim3 grid(M_TOTAL / BM, N_TOTAL / BN);   // (64, 86): x walks M tiles
    gemm_kernel<<<grid, 256, SMEM_GEMM>>>(x, d_out);
}

// round 15
// speedup vs baseline: 1.2920x; 1.2110x over previous
#include <cuda_runtime.h>
#include <cuda_fp16.h>
#include <cuda_bf16.h>
#include <cstdint>

// Problem constants (fixed by the dataset)
#define K_TOTAL   4096
#define N_TOTAL   11008
#define GROUP_SZ  128
#define M_TOTAL   8192          // 4*2048

// Element counts (dtype-invariant)
#define ELEMS_X      33554432   // 4*2048*4096
#define ELEMS_QW     45088768   // 11008*4096
#define ELEMS_SCALES 352256     // 11008*32
#define ELEMS_BIAS   11008

// Static device scratch
__device__ __half g_W[(size_t)N_TOTAL * K_TOTAL];   // dequantized weights, fp16
__device__ __half g_X[(size_t)ELEMS_X];             // x normalized to fp16
__device__ __half g_bias[ELEMS_BIAS];               // bias normalized to fp16

// ---------------------------------------------------------------------------
// dtype sniff: 0 = float32, 1 = float16, 2 = bfloat16
// ---------------------------------------------------------------------------
__device__ __forceinline__ int sniff_mode(const uint32_t* __restrict__ xr) {
    int half_votes = 0, small_votes = 0;
    #pragma unroll
    for (int i = 0; i < 64; i++) {
        uint32_t lo = xr[i] & 0xFFFFu;
        uint32_t e5 = (lo >> 10) & 31u;
        if (e5 >= 8u && e5 <= 20u) half_votes++;
        if (e5 <= 13u)             small_votes++;
    }
    if (half_votes < 52) return 0;
    return (small_votes >= 8) ? 1 : 2;
}

// ---------------------------------------------------------------------------
// Fused prologue kernel (grid 11008 x 256):
//   all blocks: dequant 16 weights/thread (blocks cover the full W)
//   blocks < 8192: ALSO convert x -> g_X at 16 elems/thread (skipped if fp16)
//   blocks < 43:   ALSO convert bias -> g_bias
// ---------------------------------------------------------------------------
__global__ __launch_bounds__(256) void prep_kernel(
    const void*  __restrict__ cand0,
    const void*  __restrict__ cand1,
    const float* __restrict__ scales,
    const void*  __restrict__ xr,
    const void*  __restrict__ br)
{
    __shared__ int smode;
    if (threadIdx.x == 0) smode = sniff_mode((const uint32_t*)xr);

    // --- dequant (all blocks), 16 elems/thread ---
    {
        const uint32_t* u0 = (const uint32_t*)cand0;
        bool c0_is_q = (u0[0] < 16u) && (u0[1] < 16u) && (u0[2] < 16u) && (u0[3] < 16u);
        const int*   q       = c0_is_q ? (const int*)cand0   : (const int*)cand1;
        const float* outlier = c0_is_q ? (const float*)cand1 : (const float*)cand0;

        size_t idx = ((size_t)blockIdx.x * 256 + threadIdx.x) * 16;
        int o = (int)(idx / K_TOTAL);
        int i = (int)(idx % K_TOTAL);
        float s = scales[o * (K_TOTAL / GROUP_SZ) + (i / GROUP_SZ)];

        int4   q0 = *(const int4*)(q + idx);
        int4   q1 = *(const int4*)(q + idx + 4);
        int4   q2 = *(const int4*)(q + idx + 8);
        int4   q3 = *(const int4*)(q + idx + 12);
        float4 f0 = *(const float4*)(outlier + idx);
        float4 f1 = *(const float4*)(outlier + idx + 4);
        float4 f2 = *(const float4*)(outlier + idx + 8);
        float4 f3 = *(const float4*)(outlier + idx + 12);

        __half2 h[8];
        h[0] = __floats2half2_rn(fmaf((float)q0.x, s, f0.x), fmaf((float)q0.y, s, f0.y));
        h[1] = __floats2half2_rn(fmaf((float)q0.z, s, f0.z), fmaf((float)q0.w, s, f0.w));
        h[2] = __floats2half2_rn(fmaf((float)q1.x, s, f1.x), fmaf((float)q1.y, s, f1.y));
        h[3] = __floats2half2_rn(fmaf((float)q1.z, s, f1.z), fmaf((float)q1.w, s, f1.w));
        h[4] = __floats2half2_rn(fmaf((float)q2.x, s, f2.x), fmaf((float)q2.y, s, f2.y));
        h[5] = __floats2half2_rn(fmaf((float)q2.z, s, f2.z), fmaf((float)q2.w, s, f2.w));
        h[6] = __floats2half2_rn(fmaf((float)q3.x, s, f3.x), fmaf((float)q3.y, s, f3.y));
        h[7] = __floats2half2_rn(fmaf((float)q3.z, s, f3.z), fmaf((float)q3.w, s, f3.w));
        *(uint4*)(g_W + idx)     = *(const uint4*)(h);
        *(uint4*)(g_W + idx + 8) = *(const uint4*)(h + 4);
    }

    __syncthreads();
    const int mode = smode;

    // --- x conversion (blocks < 8192, only when x is not fp16) ---
    if (mode != 1 && blockIdx.x < ELEMS_X / (256 * 16)) {
        size_t base = ((size_t)blockIdx.x * 256 + threadIdx.x) * 16;
        #pragma unroll
        for (int half8 = 0; half8 < 2; half8++) {
            size_t b8 = base + half8 * 8;
            __half2 h[4];
            if (mode == 0) {
                float4 f0 = *((const float4*)((const float*)xr + b8));
                float4 f1 = *((const float4*)((const float*)xr + b8 + 4));
                h[0] = __floats2half2_rn(f0.x, f0.y);
                h[1] = __floats2half2_rn(f0.z, f0.w);
                h[2] = __floats2half2_rn(f1.x, f1.y);
                h[3] = __floats2half2_rn(f1.z, f1.w);
            } else {
                const __nv_bfloat16* b = (const __nv_bfloat16*)xr + b8;
                #pragma unroll
                for (int j = 0; j < 4; j++)
                    h[j] = __floats2half2_rn(__bfloat162float(b[2*j]),
                                             __bfloat162float(b[2*j+1]));
            }
            *(uint4*)(g_X + b8) = *(const uint4*)h;
        }
    }

    // --- bias conversion (blocks < 43) ---
    {
        int i = blockIdx.x * 256 + threadIdx.x;
        if (i < ELEMS_BIAS) {
            float v;
            if (mode == 0)      v = ((const float*)br)[i];
            else if (mode == 1) v = __half2float(((const __half*)br)[i]);
            else                v = __bfloat162float(((const __nv_bfloat16*)br)[i]);
            g_bias[i] = __float2half_rn(v);
        }
    }
}

// ===========================================================================
// Kernel 2: mma.sync GEMM (R10 best config; cp.async issue SPREAD across the
// kk groups to kill the front-batched L1tex-queue burst).
// CTA tile 128x128x64, 8 warps (warp tile 32x64), ldmatrix.x4 fragments,
// 3-stage cp.async pipeline, padded smem stride (72 halfs), 2 CTAs/SM.
// Grid: blockIdx.x walks M tiles (wavemates share the B tile in L2).
// ===========================================================================
#define BM 128
#define BN 128
#define BK 64
#define ASTR 72                                // 64 data + 8 pad halfs (144B)
#define STAGES 3
#define KITERS (K_TOTAL / BK)                  // 64
#define A_BYTES (BM * ASTR * 2)                // 18432
#define B_BYTES (BN * ASTR * 2)                // 18432
#define STAGE_BYTES (A_BYTES + B_BYTES)        // 36864
#define SMEM_GEMM (STAGES * STAGE_BYTES)       // 110592 (2 CTAs: 216KB < 228KB)

__device__ __forceinline__ uint32_t smem_u32(const void* p) {
    uint32_t a;
    asm("{ .reg .u64 t; cvta.to.shared.u64 t, %1; cvt.u32.u64 %0, t; }" : "=r"(a) : "l"(p));
    return a;
}
__device__ __forceinline__ void cp_async16(uint32_t sp, const void* gp) {
    asm volatile("cp.async.cg.shared.global [%0], [%1], 16;\n" :: "r"(sp), "l"(gp));
}
__device__ __forceinline__ void cp_commit() { asm volatile("cp.async.commit_group;\n"); }
__device__ __forceinline__ void cp_wait1()  { asm volatile("cp.async.wait_group 1;\n"); }
__device__ __forceinline__ void cp_wait0()  { asm volatile("cp.async.wait_group 0;\n"); }

__device__ __forceinline__ void ldsm_x4(uint32_t& r0, uint32_t& r1, uint32_t& r2,
                                        uint32_t& r3, uint32_t addr) {
    asm volatile("ldmatrix.sync.aligned.m8n8.x4.shared.b16 {%0,%1,%2,%3}, [%4];"
                 : "=r"(r0), "=r"(r1), "=r"(r2), "=r"(r3) : "r"(addr));
}
__device__ __forceinline__ void mma16816(float c[4], const uint32_t a[4],
                                         uint32_t b0, uint32_t b1) {
    asm volatile(
        "mma.sync.aligned.m16n8k16.row.col.f32.f16.f16.f32 "
        "{%0,%1,%2,%3}, {%4,%5,%6,%7}, {%8,%9}, {%0,%1,%2,%3};\n"
        : "+f"(c[0]), "+f"(c[1]), "+f"(c[2]), "+f"(c[3])
        : "r"(a[0]), "r"(a[1]), "r"(a[2]), "r"(a[3]), "r"(b0), "r"(b1));
}

__global__ __launch_bounds__(256, 2) void gemm_kernel(const void* __restrict__ xr,
                                                      void* __restrict__ outp)
{
    extern __shared__ __align__(1024) char smem[];
    __shared__ int smode;

    const int tid  = threadIdx.x;
    const int warp = tid >> 5;
    const int lane = tid & 31;
    const int wm   = warp & 3;           // 4 warps along M (32 rows)
    const int wn   = warp >> 2;          // 2 warps along N (64 cols)
    const int group = lane >> 2;
    const int tg    = lane & 3;

    if (tid == 0) smode = sniff_mode((const uint32_t*)xr);
    __syncthreads();                     // smode visible before A-pointer pick
    const int mode = smode;

    const uint32_t sbase = smem_u32(smem);
    const int bm0 = blockIdx.x * BM;     // x walks M: wavemates share B in L2
    const int bn0 = blockIdx.y * BN;
    const __half* Abase = (mode == 1) ? (const __half*)xr : g_X;
    const __half* gA = Abase + (size_t)bm0 * K_TOTAL;
    const __half* gB = g_W   + (size_t)bn0 * K_TOTAL;

    // ldmatrix.x4 lane mapping: lanes 0-15 rows 0-15 @k0, lanes 16-31 @k8
    const int lane_row  = ((lane >> 3) & 1) * 8 + (lane & 7);
    const int lane_kofs = (lane >> 4) * 8;

    uint32_t aoff[2], boff[4];
    #pragma unroll
    for (int mi = 0; mi < 2; mi++)
        aoff[mi] = ((wm * 32 + mi * 16 + lane_row) * ASTR + lane_kofs) * 2;
    #pragma unroll
    for (int j = 0; j < 4; j++)
        boff[j] = A_BYTES + ((wn * 64 + j * 16 + lane_row) * ASTR + lane_kofs) * 2;

    // One quarter of a stage load: rows [32t, 32t+32) of both A and B.
    const int ldrow = tid >> 3;          // 0..31
    const int ldc   = tid & 7;
    const uint32_t sOff = ldrow * (ASTR * 2) + ldc * 16;

    auto load_chunk = [&](int buf, int k0, int t) {
        uint32_t sa = sbase + buf * STAGE_BYTES + sOff + t * 32 * (ASTR * 2);
        cp_async16(sa, gA + (size_t)(ldrow + t * 32) * K_TOTAL + k0 + ldc * 8);
        cp_async16(sa + A_BYTES, gB + (size_t)(ldrow + t * 32) * K_TOTAL + k0 + ldc * 8);
    };
    auto load_stage = [&](int buf, int k0) {
        #pragma unroll
        for (int t = 0; t < 4; t++) load_chunk(buf, k0, t);
    };

    float acc[2][8][4];
    #pragma unroll
    for (int mi = 0; mi < 2; mi++)
        #pragma unroll
        for (int ni = 0; ni < 8; ni++)
            #pragma unroll
            for (int r = 0; r < 4; r++) acc[mi][ni][r] = 0.f;

    load_stage(0, 0);       cp_commit();
    load_stage(1, BK);      cp_commit();

    for (int ks = 0; ks < KITERS; ks++) {
        const int s = ks % STAGES;
        cp_wait1();                 // stage ks resident (<=1 group pending)
        __syncthreads();            // all warps finished stage (ks-1)

        const int ld   = ks + 2;
        const bool dold = (ld < KITERS);
        const int lbuf = ld % STAGES;
        const int lk0  = ld * BK;

        const uint32_t st = sbase + s * STAGE_BYTES;
        #pragma unroll
        for (int kk = 0; kk < 4; kk++) {     // BK=64 -> 4 k16 steps per barrier
            if (dold) load_chunk(lbuf, lk0, kk);   // spread: 2 cp.async per group
            uint32_t a[2][4];
            #pragma unroll
            for (int mi = 0; mi < 2; mi++)
                ldsm_x4(a[mi][0], a[mi][1], a[mi][2], a[mi][3],
                        st + aoff[mi] + kk * 32);
            #pragma unroll
            for (int j = 0; j < 4; j++) {
                uint32_t r0, r1, r2, r3;
                ldsm_x4(r0, r1, r2, r3, st + boff[j] + kk * 32);
                #pragma unroll
                for (int mi = 0; mi < 2; mi++) {
                    mma16816(acc[mi][2*j],     a[mi], r0, r2);
                    mma16816(acc[mi][2*j + 1], a[mi], r1, r3);
                }
            }
        }
        cp_commit();                // close this iteration's load group
    }

    cp_wait0();

    // ---- Epilogue: bias add + dtype-dispatched direct writeout ----
    float2 bfb[8];
    #pragma unroll
    for (int ni = 0; ni < 8; ni++) {
        __half2 bh = *(const __half2*)(g_bias + bn0 + wn * 64 + ni * 8 + tg * 2);
        bfb[ni] = __half22float2(bh);
    }

    #pragma unroll
    for (int mi = 0; mi < 2; mi++) {
        int row0 = bm0 + wm * 32 + mi * 16 + group;
        #pragma unroll
        for (int ni = 0; ni < 8; ni++) {
            int col = bn0 + wn * 64 + ni * 8 + tg * 2;
            size_t o0 = (size_t)row0 * N_TOTAL + col;
            size_t o1 = (size_t)(row0 + 8) * N_TOTAL + col;
            float v00 = acc[mi][ni][0] + bfb[ni].x;
            float v01 = acc[mi][ni][1] + bfb[ni].y;
            float v10 = acc[mi][ni][2] + bfb[ni].x;
            float v11 = acc[mi][ni][3] + bfb[ni].y;
            if (mode == 1) {
                __half* O = (__half*)outp;
                *(__half2*)(O + o0) = __floats2half2_rn(v00, v01);
                *(__half2*)(O + o1) = __floats2half2_rn(v10, v11);
            } else if (mode == 0) {
                float* O = (float*)outp;
                *(float2*)(O + o0) = make_float2(v00, v01);
                *(float2*)(O + o1) = make_float2(v10, v11);
            } else {
                __nv_bfloat16* O = (__nv_bfloat16*)outp;
                *(__nv_bfloat162*)(O + o0) = __floats2bfloat162_rn(v00, v01);
                *(__nv_bfloat162*)(O + o1) = __floats2bfloat162_rn(v10, v11);
            }
        }
    }
}

// ---------------------------------------------------------------------------
// Launch
// ---------------------------------------------------------------------------
extern "C" void kernel_launch(void* const* d_in, const int* in_sizes, int n_in,
                              void* d_out, int out_size)
{
    const void* x      = nullptr;
    const void* bias   = nullptr;
    const float* scales = nullptr;
    const void* cand0  = nullptr;
    const void* cand1  = nullptr;

    for (int i = 0; i < n_in; i++) {
        long long s = in_sizes[i];
        if (s == ELEMS_X || s == 2LL*ELEMS_X || s == 4LL*ELEMS_X)               x = d_in[i];
        else if (s == ELEMS_BIAS || s == 2LL*ELEMS_BIAS || s == 4LL*ELEMS_BIAS) bias = d_in[i];
        else if (s == ELEMS_SCALES || s == 4LL*ELEMS_SCALES)                    scales = (const float*)d_in[i];
        else if (s == ELEMS_QW || s == 4LL*ELEMS_QW) {
            if (!cand0) cand0 = d_in[i]; else cand1 = d_in[i];
        }
    }
    if (!x || !bias || !scales || !cand0 || !cand1) {
        x      = d_in[0];
        cand0  = d_in[1];
        scales = (const float*)d_in[2];
        cand1  = d_in[3];
        bias   = d_in[4];
    }

    // Fused prologue: dequant + x-conv + bias-conv in one launch.
    prep_kernel<<<(int)((size_t)N_TOTAL * K_TOTAL / 16 / 256), 256>>>(
        cand0, cand1, scales, x, bias);

    cudaFuncSetAttribute(gemm_kernel, cudaFuncAttributeMaxDynamicSharedMemorySize, SMEM_GEMM);
    dim3 grid(M_TOTAL / BM, N_TOTAL / BN);   // (64, 86): x walks M tiles
    gemm_kernel<<<grid, 256, SMEM_GEMM>>>(x, d_out);
}

// round 16
// speedup vs baseline: 1.3610x; 1.0534x over previous
#include <cuda_runtime.h>
#include <cuda_fp16.h>
#include <cuda_bf16.h>
#include <cstdint>

// Problem constants (fixed by the dataset)
#define K_TOTAL   4096
#define N_TOTAL   11008
#define GROUP_SZ  128
#define M_TOTAL   8192          // 4*2048

// Element counts (dtype-invariant)
#define ELEMS_X      33554432   // 4*2048*4096
#define ELEMS_QW     45088768   // 11008*4096
#define ELEMS_SCALES 352256     // 11008*32
#define ELEMS_BIAS   11008

// Static device scratch
__device__ __half g_W[(size_t)N_TOTAL * K_TOTAL];   // dequantized weights, fp16
__device__ __half g_X[(size_t)ELEMS_X];             // x normalized to fp16
__device__ __half g_bias[ELEMS_BIAS];               // bias normalized to fp16

// ---------------------------------------------------------------------------
// dtype sniff: 0 = float32, 1 = float16, 2 = bfloat16
// ---------------------------------------------------------------------------
__device__ __forceinline__ int sniff_mode(const uint32_t* __restrict__ xr) {
    int half_votes = 0, small_votes = 0;
    #pragma unroll
    for (int i = 0; i < 64; i++) {
        uint32_t lo = xr[i] & 0xFFFFu;
        uint32_t e5 = (lo >> 10) & 31u;
        if (e5 >= 8u && e5 <= 20u) half_votes++;
        if (e5 <= 13u)             small_votes++;
    }
    if (half_votes < 52) return 0;
    return (small_votes >= 8) ? 1 : 2;
}

// ---------------------------------------------------------------------------
// Fused prologue kernel (grid 11008 x 256):
//   all blocks: dequant 16 weights/thread
//   blocks < 8192: ALSO convert x -> g_X at 16 elems/thread (skipped if fp16)
//   blocks < 43:   ALSO convert bias -> g_bias
// ---------------------------------------------------------------------------
__global__ __launch_bounds__(256) void prep_kernel(
    const void*  __restrict__ cand0,
    const void*  __restrict__ cand1,
    const float* __restrict__ scales,
    const void*  __restrict__ xr,
    const void*  __restrict__ br)
{
    __shared__ int smode;
    if (threadIdx.x == 0) smode = sniff_mode((const uint32_t*)xr);

    // --- dequant (all blocks), 16 elems/thread ---
    {
        const uint32_t* u0 = (const uint32_t*)cand0;
        bool c0_is_q = (u0[0] < 16u) && (u0[1] < 16u) && (u0[2] < 16u) && (u0[3] < 16u);
        const int*   q       = c0_is_q ? (const int*)cand0   : (const int*)cand1;
        const float* outlier = c0_is_q ? (const float*)cand1 : (const float*)cand0;

        size_t idx = ((size_t)blockIdx.x * 256 + threadIdx.x) * 16;
        int o = (int)(idx / K_TOTAL);
        int i = (int)(idx % K_TOTAL);
        float s = scales[o * (K_TOTAL / GROUP_SZ) + (i / GROUP_SZ)];

        int4   q0 = *(const int4*)(q + idx);
        int4   q1 = *(const int4*)(q + idx + 4);
        int4   q2 = *(const int4*)(q + idx + 8);
        int4   q3 = *(const int4*)(q + idx + 12);
        float4 f0 = *(const float4*)(outlier + idx);
        float4 f1 = *(const float4*)(outlier + idx + 4);
        float4 f2 = *(const float4*)(outlier + idx + 8);
        float4 f3 = *(const float4*)(outlier + idx + 12);

        __half2 h[8];
        h[0] = __floats2half2_rn(fmaf((float)q0.x, s, f0.x), fmaf((float)q0.y, s, f0.y));
        h[1] = __floats2half2_rn(fmaf((float)q0.z, s, f0.z), fmaf((float)q0.w, s, f0.w));
        h[2] = __floats2half2_rn(fmaf((float)q1.x, s, f1.x), fmaf((float)q1.y, s, f1.y));
        h[3] = __floats2half2_rn(fmaf((float)q1.z, s, f1.z), fmaf((float)q1.w, s, f1.w));
        h[4] = __floats2half2_rn(fmaf((float)q2.x, s, f2.x), fmaf((float)q2.y, s, f2.y));
        h[5] = __floats2half2_rn(fmaf((float)q2.z, s, f2.z), fmaf((float)q2.w, s, f2.w));
        h[6] = __floats2half2_rn(fmaf((float)q3.x, s, f3.x), fmaf((float)q3.y, s, f3.y));
        h[7] = __floats2half2_rn(fmaf((float)q3.z, s, f3.z), fmaf((float)q3.w, s, f3.w));
        *(uint4*)(g_W + idx)     = *(const uint4*)(h);
        *(uint4*)(g_W + idx + 8) = *(const uint4*)(h + 4);
    }

    __syncthreads();
    const int mode = smode;

    // --- x conversion (blocks < 8192, only when x is not fp16) ---
    if (mode != 1 && blockIdx.x < ELEMS_X / (256 * 16)) {
        size_t base = ((size_t)blockIdx.x * 256 + threadIdx.x) * 16;
        #pragma unroll
        for (int half8 = 0; half8 < 2; half8++) {
            size_t b8 = base + half8 * 8;
            __half2 h[4];
            if (mode == 0) {
                float4 f0 = *((const float4*)((const float*)xr + b8));
                float4 f1 = *((const float4*)((const float*)xr + b8 + 4));
                h[0] = __floats2half2_rn(f0.x, f0.y);
                h[1] = __floats2half2_rn(f0.z, f0.w);
                h[2] = __floats2half2_rn(f1.x, f1.y);
                h[3] = __floats2half2_rn(f1.z, f1.w);
            } else {
                const __nv_bfloat16* b = (const __nv_bfloat16*)xr + b8;
                #pragma unroll
                for (int j = 0; j < 4; j++)
                    h[j] = __floats2half2_rn(__bfloat162float(b[2*j]),
                                             __bfloat162float(b[2*j+1]));
            }
            *(uint4*)(g_X + b8) = *(const uint4*)h;
        }
    }

    // --- bias conversion (blocks < 43) ---
    {
        int i = blockIdx.x * 256 + threadIdx.x;
        if (i < ELEMS_BIAS) {
            float v;
            if (mode == 0)      v = ((const float*)br)[i];
            else if (mode == 1) v = __half2float(((const __half*)br)[i]);
            else                v = __bfloat162float(((const __nv_bfloat16*)br)[i]);
            g_bias[i] = __float2half_rn(v);
        }
    }
}

// ===========================================================================
// Kernel 2: mma.sync GEMM (R15 winner + pointer strength-reduction).
// CTA tile 128x128x64, 8 warps (warp tile 32x64), ldmatrix.x4 fragments,
// 3-stage cp.async pipeline with loads SPREAD across kk groups,
// running-pointer addressing (no per-chunk IMAD chains), 2 CTAs/SM.
// Grid: blockIdx.x walks M tiles (wavemates share the B tile in L2).
// ===========================================================================
#define BM 128
#define BN 128
#define BK 64
#define ASTR 72                                // 64 data + 8 pad halfs (144B)
#define STAGES 3
#define KITERS (K_TOTAL / BK)                  // 64
#define A_BYTES (BM * ASTR * 2)                // 18432
#define B_BYTES (BN * ASTR * 2)                // 18432
#define STAGE_BYTES (A_BYTES + B_BYTES)        // 36864
#define SMEM_GEMM (STAGES * STAGE_BYTES)       // 110592 (2 CTAs: 216KB < 228KB)

__device__ __forceinline__ uint32_t smem_u32(const void* p) {
    uint32_t a;
    asm("{ .reg .u64 t; cvta.to.shared.u64 t, %1; cvt.u32.u64 %0, t; }" : "=r"(a) : "l"(p));
    return a;
}
__device__ __forceinline__ void cp_async16(uint32_t sp, const void* gp) {
    asm volatile("cp.async.cg.shared.global [%0], [%1], 16;\n" :: "r"(sp), "l"(gp));
}
__device__ __forceinline__ void cp_commit() { asm volatile("cp.async.commit_group;\n"); }
__device__ __forceinline__ void cp_wait1()  { asm volatile("cp.async.wait_group 1;\n"); }
__device__ __forceinline__ void cp_wait0()  { asm volatile("cp.async.wait_group 0;\n"); }

__device__ __forceinline__ void ldsm_x4(uint32_t& r0, uint32_t& r1, uint32_t& r2,
                                        uint32_t& r3, uint32_t addr) {
    asm volatile("ldmatrix.sync.aligned.m8n8.x4.shared.b16 {%0,%1,%2,%3}, [%4];"
                 : "=r"(r0), "=r"(r1), "=r"(r2), "=r"(r3) : "r"(addr));
}
__device__ __forceinline__ void mma16816(float c[4], const uint32_t a[4],
                                         uint32_t b0, uint32_t b1) {
    asm volatile(
        "mma.sync.aligned.m16n8k16.row.col.f32.f16.f16.f32 "
        "{%0,%1,%2,%3}, {%4,%5,%6,%7}, {%8,%9}, {%0,%1,%2,%3};\n"
        : "+f"(c[0]), "+f"(c[1]), "+f"(c[2]), "+f"(c[3])
        : "r"(a[0]), "r"(a[1]), "r"(a[2]), "r"(a[3]), "r"(b0), "r"(b1));
}

__global__ __launch_bounds__(256, 2) void gemm_kernel(const void* __restrict__ xr,
                                                      void* __restrict__ outp)
{
    extern __shared__ __align__(1024) char smem[];
    __shared__ int smode;

    const int tid  = threadIdx.x;
    const int warp = tid >> 5;
    const int lane = tid & 31;
    const int wm   = warp & 3;           // 4 warps along M (32 rows)
    const int wn   = warp >> 2;          // 2 warps along N (64 cols)
    const int group = lane >> 2;
    const int tg    = lane & 3;

    if (tid == 0) smode = sniff_mode((const uint32_t*)xr);
    __syncthreads();                     // smode visible before A-pointer pick
    const int mode = smode;

    const uint32_t sbase = smem_u32(smem);
    const int bm0 = blockIdx.x * BM;     // x walks M: wavemates share B in L2
    const int bn0 = blockIdx.y * BN;
    const __half* Abase = (mode == 1) ? (const __half*)xr : g_X;

    // ldmatrix.x4 lane mapping: lanes 0-15 rows 0-15 @k0, lanes 16-31 @k8
    const int lane_row  = ((lane >> 3) & 1) * 8 + (lane & 7);
    const int lane_kofs = (lane >> 4) * 8;

    uint32_t aoff[2], boff[4];
    #pragma unroll
    for (int mi = 0; mi < 2; mi++)
        aoff[mi] = ((wm * 32 + mi * 16 + lane_row) * ASTR + lane_kofs) * 2;
    #pragma unroll
    for (int j = 0; j < 4; j++)
        boff[j] = A_BYTES + ((wn * 64 + j * 16 + lane_row) * ASTR + lane_kofs) * 2;

    // Per-thread load bases (hoisted once; all later addressing is +const)
    const int ldrow = tid >> 3;          // 0..31
    const int ldc   = tid & 7;
    const uint32_t sOff = ldrow * (ASTR * 2) + ldc * 16;
    const __half* pA = Abase + (size_t)(bm0 + ldrow) * K_TOTAL + ldc * 8;
    const __half* pB = g_W   + (size_t)(bn0 + ldrow) * K_TOTAL + ldc * 8;

    float acc[2][8][4];
    #pragma unroll
    for (int mi = 0; mi < 2; mi++)
        #pragma unroll
        for (int ni = 0; ni < 8; ni++)
            #pragma unroll
            for (int r = 0; r < 4; r++) acc[mi][ni][r] = 0.f;

    // Prologue: stages 0 and 1, one commit each
    #pragma unroll
    for (int t = 0; t < 4; t++) {
        cp_async16(sbase + sOff + t * 32 * (ASTR * 2),
                   pA + (size_t)t * 32 * K_TOTAL);
        cp_async16(sbase + A_BYTES + sOff + t * 32 * (ASTR * 2),
                   pB + (size_t)t * 32 * K_TOTAL);
    }
    cp_commit();
    #pragma unroll
    for (int t = 0; t < 4; t++) {
        cp_async16(sbase + STAGE_BYTES + sOff + t * 32 * (ASTR * 2),
                   pA + (size_t)t * 32 * K_TOTAL + BK);
        cp_async16(sbase + STAGE_BYTES + A_BYTES + sOff + t * 32 * (ASTR * 2),
                   pB + (size_t)t * 32 * K_TOTAL + BK);
    }
    cp_commit();

    // Running cursors (strength-reduced: += and wrap, no mul/mod)
    uint32_t stC = sbase;                        // consume-stage smem base
    uint32_t sLd = sbase + 2 * STAGE_BYTES;      // load-stage smem base
    const __half* pAc = pA + 2 * BK;             // load-stage global A
    const __half* pBc = pB + 2 * BK;             // load-stage global B
    const uint32_t sEnd = sbase + 3 * STAGE_BYTES;

    for (int ks = 0; ks < KITERS; ks++) {
        cp_wait1();                 // stage ks resident (<=1 group pending)
        __syncthreads();            // all warps finished stage (ks-1)

        const bool dold = (ks + 2 < KITERS);

        #pragma unroll
        for (int kk = 0; kk < 4; kk++) {     // BK=64 -> 4 k16 steps per barrier
            if (dold) {                      // spread: 2 cp.async per kk group
                cp_async16(sLd + sOff + kk * 32 * (ASTR * 2),
                           pAc + (size_t)kk * 32 * K_TOTAL);
                cp_async16(sLd + A_BYTES + sOff + kk * 32 * (ASTR * 2),
                           pBc + (size_t)kk * 32 * K_TOTAL);
            }
            uint32_t a[2][4];
            #pragma unroll
            for (int mi = 0; mi < 2; mi++)
                ldsm_x4(a[mi][0], a[mi][1], a[mi][2], a[mi][3],
                        stC + aoff[mi] + kk * 32);
            #pragma unroll
            for (int j = 0; j < 4; j++) {
                uint32_t r0, r1, r2, r3;
                ldsm_x4(r0, r1, r2, r3, stC + boff[j] + kk * 32);
                #pragma unroll
                for (int mi = 0; mi < 2; mi++) {
                    mma16816(acc[mi][2*j],     a[mi], r0, r2);
                    mma16816(acc[mi][2*j + 1], a[mi], r1, r3);
                }
            }
        }
        cp_commit();                // close this iteration's load group

        stC += STAGE_BYTES; if (stC == sEnd) stC = sbase;
        sLd += STAGE_BYTES; if (sLd == sEnd) sLd = sbase;
        pAc += BK; pBc += BK;
    }

    cp_wait0();

    // ---- Epilogue: bias add + dtype-dispatched direct writeout ----
    float2 bfb[8];
    #pragma unroll
    for (int ni = 0; ni < 8; ni++) {
        __half2 bh = *(const __half2*)(g_bias + bn0 + wn * 64 + ni * 8 + tg * 2);
        bfb[ni] = __half22float2(bh);
    }

    #pragma unroll
    for (int mi = 0; mi < 2; mi++) {
        int row0 = bm0 + wm * 32 + mi * 16 + group;
        #pragma unroll
        for (int ni = 0; ni < 8; ni++) {
            int col = bn0 + wn * 64 + ni * 8 + tg * 2;
            size_t o0 = (size_t)row0 * N_TOTAL + col;
            size_t o1 = (size_t)(row0 + 8) * N_TOTAL + col;
            float v00 = acc[mi][ni][0] + bfb[ni].x;
            float v01 = acc[mi][ni][1] + bfb[ni].y;
            float v10 = acc[mi][ni][2] + bfb[ni].x;
            float v11 = acc[mi][ni][3] + bfb[ni].y;
            if (mode == 1) {
                __half* O = (__half*)outp;
                *(__half2*)(O + o0) = __floats2half2_rn(v00, v01);
                *(__half2*)(O + o1) = __floats2half2_rn(v10, v11);
            } else if (mode == 0) {
                float* O = (float*)outp;
                *(float2*)(O + o0) = make_float2(v00, v01);
                *(float2*)(O + o1) = make_float2(v10, v11);
            } else {
                __nv_bfloat16* O = (__nv_bfloat16*)outp;
                *(__nv_bfloat162*)(O + o0) = __floats2bfloat162_rn(v00, v01);
                *(__nv_bfloat162*)(O + o1) = __floats2bfloat162_rn(v10, v11);
            }
        }
    }
}

// ---------------------------------------------------------------------------
// Launch
// ---------------------------------------------------------------------------
extern "C" void kernel_launch(void* const* d_in, const int* in_sizes, int n_in,
                              void* d_out, int out_size)
{
    const void* x      = nullptr;
    const void* bias   = nullptr;
    const float* scales = nullptr;
    const void* cand0  = nullptr;
    const void* cand1  = nullptr;

    for (int i = 0; i < n_in; i++) {
        long long s = in_sizes[i];
        if (s == ELEMS_X || s == 2LL*ELEMS_X || s == 4LL*ELEMS_X)               x = d_in[i];
        else if (s == ELEMS_BIAS || s == 2LL*ELEMS_BIAS || s == 4LL*ELEMS_BIAS) bias = d_in[i];
        else if (s == ELEMS_SCALES || s == 4LL*ELEMS_SCALES)                    scales = (const float*)d_in[i];
        else if (s == ELEMS_QW || s == 4LL*ELEMS_QW) {
            if (!cand0) cand0 = d_in[i]; else cand1 = d_in[i];
        }
    }
    if (!x || !bias || !scales || !cand0 || !cand1) {
        x      = d_in[0];
        cand0  = d_in[1];
        scales = (const float*)d_in[2];
        cand1  = d_in[3];
        bias   = d_in[4];
    }

    // Fused prologue: dequant + x-conv + bias-conv in one launch.
    prep_kernel<<<(int)((size_t)N_TOTAL * K_TOTAL / 16 / 256), 256>>>(
        cand0, cand1, scales, x, bias);

    cudaFuncSetAttribute(gemm_kernel, cudaFuncAttributeMaxDynamicSharedMemorySize, SMEM_GEMM);
    dim3 grid(M_TOTAL / BM, N_TOTAL / BN);   // (64, 86): x walks M tiles
    gemm_kernel<<<grid, 256, SMEM_GEMM>>>(x, d_out);
}